// round 2
// baseline (speedup 1.0000x reference)
#include <cuda_runtime.h>
#include <cuda_fp16.h>
#include <math.h>
#include <float.h>

#define HH 320
#define WW 512
#define HW (HH * WW)
#define NDISP 64
#define RAD 10          // BLOCK=21 -> radius 10
#define NIMGB 4         // (img in {x,gt}) * (b in {0,1})
#define DG 4            // disparities per CTA in kvert
#define WS 64           // w-strip width in kvert

// Scratch (device globals -- allocation-free rule)
__device__ float  g_norm[NIMGB * 6 * HW];        // normalized L/R, 15.7 MB
__device__ __half g_V[NIMGB * NDISP * HW];       // vertical box sums, 84 MB (fp16)
__device__ float  g_disp[NIMGB * HW];            // disparity maps (as float)
__device__ float  g_part[64];                    // reduction partials

// ---------------------------------------------------------------------------
// K1: per-pixel 3-channel L2 normalize.
// ---------------------------------------------------------------------------
__global__ void knorm(const float* __restrict__ x, const float* __restrict__ gt) {
    int idx = blockIdx.x * blockDim.x + threadIdx.x;
    const int total = NIMGB * 2 * HW;
    if (idx >= total) return;
    int pix  = idx % HW;
    int rest = idx / HW;
    int side = rest & 1;
    int imgb = rest >> 1;
    int img  = imgb >> 1;
    int b    = imgb & 1;

    const float* src = img ? gt : x;
    int base = (b * 6 + side * 3) * HW + pix;
    float v0 = src[base];
    float v1 = src[base + HW];
    float v2 = src[base + 2 * HW];
    float n = sqrtf(v0 * v0 + v1 * v1 + v2 * v2);
    float inv = 1.0f / fmaxf(n, 1e-12f);
    int dst = (imgb * 6 + side * 3) * HW + pix;
    g_norm[dst]          = v0 * inv;
    g_norm[dst + HW]     = v1 * inv;
    g_norm[dst + 2 * HW] = v2 * inv;
}

// ---------------------------------------------------------------------------
// K2: vertical 21-tap box of SAD, 4 disparities per thread with smem-staged
// L/R rows (global loads shared across the d-group) and fp16 history buffer
// (quantize-consistent add/sub -> no drift). Double-buffered stage + prefetch.
// grid (WW/WS=8, NDISP/DG=16, NIMGB=4), WS=64 threads.
// ---------------------------------------------------------------------------
__global__ void kvert() {
    int tid  = threadIdx.x;             // 0..63
    int w0   = blockIdx.x * WS;
    int w    = w0 + tid;
    int d0   = blockIdx.y * DG;
    int imgb = blockIdx.z;

    const float* __restrict__ L = g_norm + imgb * 6 * HW;   // ch 0..2
    const float* __restrict__ R = L + 3 * HW;               // ch 3..5
    __half* __restrict__ V = g_V + imgb * NDISP * HW;

    __shared__ float sL[2][3][WS];
    __shared__ float sR[2][3][WS + 8];          // need WS+DG-1 = 67, pad to 72
    __shared__ unsigned hist[21][2][WS];        // half2-packed SAD history

    // zero history (each thread touches only its own column -> no sync needed)
#pragma unroll
    for (int s = 0; s < 21; ++s) { hist[s][0][tid] = 0u; hist[s][1][tid] = 0u; }

    const int rbase = w0 - d0 - (DG - 1);       // global w-index of sR[...][0]

    float run0 = 0.f, run1 = 0.f, run2 = 0.f, run3 = 0.f;
    int slot = 0;

    float pl0, pl1, pl2, pr0, pr1, pr2, pe0, pe1, pe2;
    // prefetch row 0
    {
        int base = 0;
        pl0 = L[base + w]; pl1 = L[HW + base + w]; pl2 = L[2 * HW + base + w];
        int rg = rbase + tid;
        bool v = (rg >= 0);
        pr0 = v ? R[base + rg] : 0.f;
        pr1 = v ? R[HW + base + rg] : 0.f;
        pr2 = v ? R[2 * HW + base + rg] : 0.f;
        pe0 = pe1 = pe2 = 0.f;
        if (tid < DG - 1) {
            int rg2 = rbase + WS + tid;
            if (rg2 >= 0) {
                pe0 = R[base + rg2]; pe1 = R[HW + base + rg2]; pe2 = R[2 * HW + base + rg2];
            }
        }
    }

    for (int j = 0; j < HH + RAD; ++j) {
        int cur = j & 1;
        // commit prefetched row j to stage
        sL[cur][0][tid] = pl0; sL[cur][1][tid] = pl1; sL[cur][2][tid] = pl2;
        sR[cur][0][tid] = pr0; sR[cur][1][tid] = pr1; sR[cur][2][tid] = pr2;
        if (tid < DG - 1) {
            sR[cur][0][WS + tid] = pe0; sR[cur][1][WS + tid] = pe1; sR[cur][2][WS + tid] = pe2;
        }
        __syncthreads();

        // prefetch row j+1 (overlaps with compute below)
        int jn = j + 1;
        if (jn < HH) {
            int base = jn * WW;
            pl0 = L[base + w]; pl1 = L[HW + base + w]; pl2 = L[2 * HW + base + w];
            int rg = rbase + tid;
            bool v = (rg >= 0);
            pr0 = v ? R[base + rg] : 0.f;
            pr1 = v ? R[HW + base + rg] : 0.f;
            pr2 = v ? R[2 * HW + base + rg] : 0.f;
            pe0 = pe1 = pe2 = 0.f;
            if (tid < DG - 1) {
                int rg2 = rbase + WS + tid;
                if (rg2 >= 0) {
                    pe0 = R[base + rg2]; pe1 = R[HW + base + rg2]; pe2 = R[2 * HW + base + rg2];
                }
            }
        } else {
            pl0 = pl1 = pl2 = pr0 = pr1 = pr2 = pe0 = pe1 = pe2 = 0.f;
        }

        // compute SAD for 4 disparities from stage (zeros for j >= HH)
        float l0 = sL[cur][0][tid], l1 = sL[cur][1][tid], l2 = sL[cur][2][tid];

        int si0 = tid + 3, si1 = tid + 2, si2 = tid + 1, si3 = tid;   // dl=0..3
        float dn0 = fabsf(l0 - sR[cur][0][si0]) + fabsf(l1 - sR[cur][1][si0]) + fabsf(l2 - sR[cur][2][si0]);
        float dn1 = fabsf(l0 - sR[cur][0][si1]) + fabsf(l1 - sR[cur][1][si1]) + fabsf(l2 - sR[cur][2][si1]);
        float dn2 = fabsf(l0 - sR[cur][0][si2]) + fabsf(l1 - sR[cur][1][si2]) + fabsf(l2 - sR[cur][2][si2]);
        float dn3 = fabsf(l0 - sR[cur][0][si3]) + fabsf(l1 - sR[cur][1][si3]) + fabsf(l2 - sR[cur][2][si3]);

        unsigned u0 = (unsigned)__half_as_ushort(__float2half_rn(dn0));
        unsigned u1 = (unsigned)__half_as_ushort(__float2half_rn(dn1));
        unsigned u2 = (unsigned)__half_as_ushort(__float2half_rn(dn2));
        unsigned u3 = (unsigned)__half_as_ushort(__float2half_rn(dn3));

        unsigned op0 = hist[slot][0][tid];
        unsigned op1 = hist[slot][1][tid];
        hist[slot][0][tid] = u0 | (u1 << 16);
        hist[slot][1][tid] = u2 | (u3 << 16);

        run0 += __half2float(__ushort_as_half((unsigned short)u0))
              - __half2float(__ushort_as_half((unsigned short)(op0 & 0xffffu)));
        run1 += __half2float(__ushort_as_half((unsigned short)u1))
              - __half2float(__ushort_as_half((unsigned short)(op0 >> 16)));
        run2 += __half2float(__ushort_as_half((unsigned short)u2))
              - __half2float(__ushort_as_half((unsigned short)(op1 & 0xffffu)));
        run3 += __half2float(__ushort_as_half((unsigned short)u3))
              - __half2float(__ushort_as_half((unsigned short)(op1 >> 16)));

        int h = j - RAD;
        if (h >= 0) {
            int ob = h * WW + w;
            V[(d0 + 0) * HW + ob] = __float2half_rn(run0);
            V[(d0 + 1) * HW + ob] = __float2half_rn(run1);
            V[(d0 + 2) * HW + ob] = __float2half_rn(run2);
            V[(d0 + 3) * HW + ob] = __float2half_rn(run3);
        }
        slot = (slot + 1 == 21) ? 0 : slot + 1;
        // single sync per row is sufficient: next iteration writes the OTHER
        // stage buffer; the sync after its STS protects buffer reuse at j+2.
    }
}

// ---------------------------------------------------------------------------
// K3: horizontal 21-tap box + argmin over d. CTA = (imgb, 4-row tile),
// 256 threads; thread owns 8 consecutive w with sliding horizontal sum.
// Padded smem (w -> w + w/8) makes the stride-8 lane pattern conflict-free.
// ---------------------------------------------------------------------------
#define PADW(q) ((q) + ((q) >> 3))
#define ROWSTR 576   // PADW(511)=574, pad to 576

__global__ void khoriz() {
    __shared__ float rows[4 * ROWSTR];

    int t     = threadIdx.x;      // 0..255
    int imgb  = blockIdx.y;
    int h0    = blockIdx.x * 4;
    int hloc  = t >> 6;           // 0..3
    int c     = t & 63;
    int wbase = c * 8;

    float bestc[8];
    int   bestd[8];
#pragma unroll
    for (int i = 0; i < 8; ++i) { bestc[i] = FLT_MAX; bestd[i] = 0; }

    const __half* __restrict__ Vb = g_V + imgb * NDISP * HW;

    for (int d = 0; d < NDISP; ++d) {
        __syncthreads();
        const __half* __restrict__ Vd = Vb + d * HW + h0 * WW;
#pragma unroll
        for (int k = t; k < 1024; k += 256) {
            int r  = k >> 8;              // 0..3
            int w2 = (k & 255) * 2;       // even
            __half2 hv = *reinterpret_cast<const __half2*>(Vd + r * WW + w2);
            float2 f = __half22float2(hv);
            rows[r * ROWSTR + PADW(w2)]     = f.x;
            rows[r * ROWSTR + PADW(w2) + 1] = f.y;   // w2 even -> same pad bucket
        }
        __syncthreads();

        const float* row = &rows[hloc * ROWSTR];
        float s = 0.0f;
        int lo = wbase - RAD; if (lo < 0) lo = 0;
        int hi = wbase + RAD; if (hi > WW - 1) hi = WW - 1;
        for (int ww = lo; ww <= hi; ++ww) s += row[PADW(ww)];

        int w = wbase;
#pragma unroll
        for (int i = 0; i < 8; ++i) {
            if (s < bestc[i]) { bestc[i] = s; bestd[i] = d; }
            int add = w + RAD + 1;
            int sub = w - RAD;
            if (add < WW) s += row[PADW(add)];
            if (sub >= 0) s -= row[PADW(sub)];
            ++w;
        }
    }

    float* __restrict__ D = g_disp + imgb * HW + (h0 + hloc) * WW + wbase;
#pragma unroll
    for (int i = 0; i < 8; ++i) D[i] = (float)bestd[i];
}

// ---------------------------------------------------------------------------
// K4/K5: deterministic two-stage reduction of |disp_x - disp_gt|.
// ---------------------------------------------------------------------------
__global__ void kred1() {
    __shared__ float sm[256];
    const int N = 2 * HW;
    int tid = threadIdx.x;
    float s = 0.0f;
    for (int p = blockIdx.x * 256 + tid; p < N; p += 64 * 256)
        s += fabsf(g_disp[p] - g_disp[2 * HW + p]);
    sm[tid] = s;
    __syncthreads();
    for (int o = 128; o > 0; o >>= 1) {
        if (tid < o) sm[tid] += sm[tid + o];
        __syncthreads();
    }
    if (tid == 0) g_part[blockIdx.x] = sm[0];
}

__global__ void kred2(float* __restrict__ out) {
    __shared__ float sm[64];
    int tid = threadIdx.x;   // 64 threads
    sm[tid] = g_part[tid];
    __syncthreads();
    for (int o = 32; o > 0; o >>= 1) {
        if (tid < o) sm[tid] += sm[tid + o];
        __syncthreads();
    }
    if (tid == 0) out[0] = sm[0] / (float)(2 * HW);
}

// ---------------------------------------------------------------------------
extern "C" void kernel_launch(void* const* d_in, const int* in_sizes, int n_in,
                              void* d_out, int out_size) {
    const float* x  = (const float*)d_in[0];
    const float* gt = (const float*)d_in[1];
    float* out = (float*)d_out;

    int nNorm = NIMGB * 2 * HW;
    knorm<<<(nNorm + 255) / 256, 256>>>(x, gt);
    kvert<<<dim3(WW / WS, NDISP / DG, NIMGB), WS>>>();
    khoriz<<<dim3(HH / 4, NIMGB), 256>>>();
    kred1<<<64, 256>>>();
    kred2<<<1, 64>>>(out);
}

// round 3
// speedup vs baseline: 1.8832x; 1.8832x over previous
#include <cuda_runtime.h>
#include <cuda_fp16.h>
#include <math.h>
#include <float.h>

#define HH 320
#define WW 512
#define HW (HH * WW)
#define NDISP 64
#define RAD 10
#define NIMGB 4

// Scratch (device globals -- allocation-free rule)
__device__ __align__(16) __half2 g_normh[NIMGB * 2 * HW * 2]; // packed (c0c1)(c2,0), 10.5 MB
__device__ __align__(16) __half  g_V[NIMGB * HH * WW * NDISP]; // layout [imgb][h][w][d], 84 MB
__device__ float g_disp[NIMGB * HW];
__device__ float g_part[256];

// ---------------------------------------------------------------------------
// K1: L2-normalize, output packed fp16 (4 halves per pixel per side).
// ---------------------------------------------------------------------------
__global__ void knorm(const float* __restrict__ x, const float* __restrict__ gt) {
    int idx = blockIdx.x * blockDim.x + threadIdx.x;
    const int total = NIMGB * 2 * HW;
    if (idx >= total) return;
    int pix  = idx % HW;
    int rest = idx / HW;
    int side = rest & 1;
    int imgb = rest >> 1;
    int img  = imgb >> 1;
    int b    = imgb & 1;

    const float* src = img ? gt : x;
    int base = (b * 6 + side * 3) * HW + pix;
    float v0 = src[base];
    float v1 = src[base + HW];
    float v2 = src[base + 2 * HW];
    float n = sqrtf(v0 * v0 + v1 * v1 + v2 * v2);
    float inv = 1.0f / fmaxf(n, 1e-12f);

    __half2 a = __floats2half2_rn(v0 * inv, v1 * inv);
    __half2 c = __floats2half2_rn(v2 * inv, 0.0f);
    uint2 pk;
    pk.x = *reinterpret_cast<unsigned*>(&a);
    pk.y = *reinterpret_cast<unsigned*>(&c);
    uint2* dst = reinterpret_cast<uint2*>(g_normh + ((size_t)(imgb * 2 + side) * HW + pix) * 2);
    *dst = pk;
}

// ---------------------------------------------------------------------------
// K2: vertical 21-tap box of SAD. Thread = (d = tid&63, wloc = tid>>6).
// CTA covers 64 d x 8 w; NO syncthreads (per-thread smem history column).
// d-reuse of image rows is served by L1 (broadcast L, reversed-contig R).
// V written d-contiguous: [h][w][d].
// ---------------------------------------------------------------------------
__global__ void kvert() {
    int tid  = threadIdx.x;            // 0..511
    int d    = tid & 63;
    int wloc = tid >> 6;               // 0..7
    int imgb = blockIdx.y;
    int w    = blockIdx.x * 8 + wloc;

    const uint2* __restrict__ L =
        reinterpret_cast<const uint2*>(g_normh + (size_t)(imgb * 2 + 0) * HW * 2);
    const uint2* __restrict__ R =
        reinterpret_cast<const uint2*>(g_normh + (size_t)(imgb * 2 + 1) * HW * 2);
    __half* __restrict__ V = g_V + (size_t)imgb * HH * WW * NDISP;

    __shared__ __half hist[21][512];
#pragma unroll
    for (int s = 0; s < 21; ++s) hist[s][tid] = __ushort_as_half((unsigned short)0);

    int rw = w - d;
    bool valid = (rw >= 0);
    float run = 0.0f;
    int slot = 0;

#pragma unroll 2
    for (int j = 0; j < HH + RAD; ++j) {
        float dn = 0.0f;
        if (j < HH) {
            uint2 lu = L[j * WW + w];
            __half2 l01 = *reinterpret_cast<__half2*>(&lu.x);
            __half2 l2p = *reinterpret_cast<__half2*>(&lu.y);
            float2 lf = __half22float2(l01);
            float l2 = __low2float(l2p);
            float r0 = 0.f, r1 = 0.f, r2 = 0.f;
            if (valid) {
                uint2 ru = R[j * WW + rw];
                __half2 r01 = *reinterpret_cast<__half2*>(&ru.x);
                __half2 r2p = *reinterpret_cast<__half2*>(&ru.y);
                float2 rf = __half22float2(r01);
                r0 = rf.x; r1 = rf.y; r2 = __low2float(r2p);
            }
            dn = fabsf(lf.x - r0) + fabsf(lf.y - r1) + fabsf(l2 - r2);
        }
        __half dq = __float2half_rn(dn);
        __half old = hist[slot][tid];
        hist[slot][tid] = dq;
        run += __half2float(dq) - __half2float(old);   // quantize-consistent, no drift
        int h = j - RAD;
        if (h >= 0) V[(size_t)(h * WW + w) * NDISP + d] = __float2half_rn(run);
        slot = (slot + 1 == 21) ? 0 : slot + 1;
    }
}

// ---------------------------------------------------------------------------
// K3: horizontal 21-tap box + argmin. CTA = (imgb, row). 512 threads:
// thread = (oct = t>>3 owning 8 consecutive w, dpg = t&7 owning d-pairs
// dpg, dpg+8 per pass). Two passes over d-pair halves (16 words each).
// Smem [w][17 words] padded: compute-phase banks = (8*oct + dpg) -> all 32
// distinct, conflict-free. half2 d-pair math; fp32 sliding sums.
// Exact argmin tie-break via packed (costbits<<32 | d) shfl-min (width 8).
// ---------------------------------------------------------------------------
#define SW 17

__global__ void khoriz() {
    __shared__ unsigned sm[WW * SW];   // 34.8 KB

    int t    = threadIdx.x;            // 0..511
    int oct  = t >> 3;                 // 0..63
    int dpg  = t & 7;                  // 0..7
    int imgb = blockIdx.y;
    int h    = blockIdx.x;
    int wb   = oct * 8;

    const uint4* __restrict__ G = reinterpret_cast<const uint4*>(
        g_V + ((size_t)(imgb * HH + h) * WW) * NDISP);

    float bestc[8];
    int   bestd[8];
#pragma unroll
    for (int i = 0; i < 8; ++i) { bestc[i] = FLT_MAX; bestd[i] = 0; }

#pragma unroll
    for (int pass = 0; pass < 2; ++pass) {
        __syncthreads();
        // stage d-pair words [pass*16, pass*16+16) for all 512 w
        for (int k = t; k < 2048; k += 512) {
            int w = k >> 2, q = k & 3;
            uint4 v = G[w * 8 + pass * 4 + q];
            unsigned* dst = &sm[w * SW + q * 4];
            dst[0] = v.x; dst[1] = v.y; dst[2] = v.z; dst[3] = v.w;
        }
        __syncthreads();

#pragma unroll
        for (int p = 0; p < 2; ++p) {
            int dpl = dpg + p * 8;                  // local word 0..15
            int dbase = (pass * 16 + dpl) * 2;      // actual disparity (even)

            float sx = 0.f, sy = 0.f;
#pragma unroll
            for (int u = 0; u < 21; ++u) {
                int ww = wb - RAD + u;
                if (ww >= 0 && ww < WW) {
                    float2 f = __half22float2(
                        *reinterpret_cast<const __half2*>(&sm[ww * SW + dpl]));
                    sx += f.x; sy += f.y;
                }
            }
            int w = wb;
#pragma unroll
            for (int i = 0; i < 8; ++i) {
                if (sx < bestc[i]) { bestc[i] = sx; bestd[i] = dbase; }
                if (sy < bestc[i]) { bestc[i] = sy; bestd[i] = dbase + 1; }
                int add = w + RAD + 1;
                int sub = w - RAD;
                if (add < WW) {
                    float2 f = __half22float2(
                        *reinterpret_cast<const __half2*>(&sm[add * SW + dpl]));
                    sx += f.x; sy += f.y;
                }
                if (sub >= 0) {
                    float2 f = __half22float2(
                        *reinterpret_cast<const __half2*>(&sm[sub * SW + dpl]));
                    sx -= f.x; sy -= f.y;
                }
                ++w;
            }
        }
    }

    // reduce over the 8 dpg lanes (same oct) -- packed min keeps smallest d on tie
    float* __restrict__ D = g_disp + (imgb * HH + h) * WW;
#pragma unroll
    for (int i = 0; i < 8; ++i) {
        unsigned long long key =
            ((unsigned long long)__float_as_uint(bestc[i]) << 32) | (unsigned)bestd[i];
#pragma unroll
        for (int m = 4; m >= 1; m >>= 1) {
            unsigned long long o = __shfl_xor_sync(0xffffffffu, key, m, 8);
            if (o < key) key = o;
        }
        if (dpg == 0) D[wb + i] = (float)(unsigned)(key & 0xffffffffULL);
    }
}

// ---------------------------------------------------------------------------
// K4/K5: deterministic two-stage reduction of |disp_x - disp_gt|.
// ---------------------------------------------------------------------------
__global__ void kred1() {
    __shared__ float sm[256];
    const int N = 2 * HW;
    int tid = threadIdx.x;
    float s = 0.0f;
    for (int p = blockIdx.x * 256 + tid; p < N; p += 256 * 256)
        s += fabsf(g_disp[p] - g_disp[2 * HW + p]);
    sm[tid] = s;
    __syncthreads();
    for (int o = 128; o > 0; o >>= 1) {
        if (tid < o) sm[tid] += sm[tid + o];
        __syncthreads();
    }
    if (tid == 0) g_part[blockIdx.x] = sm[0];
}

__global__ void kred2(float* __restrict__ out) {
    __shared__ float sm[256];
    int tid = threadIdx.x;
    sm[tid] = g_part[tid];
    __syncthreads();
    for (int o = 128; o > 0; o >>= 1) {
        if (tid < o) sm[tid] += sm[tid + o];
        __syncthreads();
    }
    if (tid == 0) out[0] = sm[0] / (float)(2 * HW);
}

// ---------------------------------------------------------------------------
extern "C" void kernel_launch(void* const* d_in, const int* in_sizes, int n_in,
                              void* d_out, int out_size) {
    const float* x  = (const float*)d_in[0];
    const float* gt = (const float*)d_in[1];
    float* out = (float*)d_out;

    int nNorm = NIMGB * 2 * HW;
    knorm<<<(nNorm + 255) / 256, 256>>>(x, gt);
    kvert<<<dim3(WW / 8, NIMGB), 512>>>();
    khoriz<<<dim3(HH, NIMGB), 512>>>();
    kred1<<<256, 256>>>();
    kred2<<<1, 256>>>(out);
}

// round 4
// speedup vs baseline: 1.9251x; 1.0223x over previous
#include <cuda_runtime.h>
#include <cuda_fp16.h>
#include <math.h>
#include <float.h>

#define HH 320
#define WW 512
#define HW (HH * WW)
#define NDISP 64
#define RAD 10
#define NIMGB 4

// Scratch (device globals -- allocation-free rule)
__device__ __align__(16) __half2 g_normh[NIMGB * 2 * HW * 2]; // packed (c0c1)(c2,0), 10.5 MB
__device__ __align__(16) __half  g_V[(size_t)NIMGB * HH * WW * NDISP]; // [imgb][h][w][d], 84 MB
__device__ float g_disp[NIMGB * HW];
__device__ float g_part[256];

// ---------------------------------------------------------------------------
// K1: L2-normalize, output packed fp16 (4 halves per pixel per side).
// ---------------------------------------------------------------------------
__global__ void knorm(const float* __restrict__ x, const float* __restrict__ gt) {
    int idx = blockIdx.x * blockDim.x + threadIdx.x;
    const int total = NIMGB * 2 * HW;
    if (idx >= total) return;
    int pix  = idx % HW;
    int rest = idx / HW;
    int side = rest & 1;
    int imgb = rest >> 1;
    int img  = imgb >> 1;
    int b    = imgb & 1;

    const float* src = img ? gt : x;
    int base = (b * 6 + side * 3) * HW + pix;
    float v0 = src[base];
    float v1 = src[base + HW];
    float v2 = src[base + 2 * HW];
    float n = sqrtf(v0 * v0 + v1 * v1 + v2 * v2);
    float inv = 1.0f / fmaxf(n, 1e-12f);

    __half2 a = __floats2half2_rn(v0 * inv, v1 * inv);
    __half2 c = __floats2half2_rn(v2 * inv, 0.0f);
    uint2 pk;
    pk.x = *reinterpret_cast<unsigned*>(&a);
    pk.y = *reinterpret_cast<unsigned*>(&c);
    uint2* dst = reinterpret_cast<uint2*>(g_normh + ((size_t)(imgb * 2 + side) * HW + pix) * 2);
    *dst = pk;
}

// ---------------------------------------------------------------------------
// K2: vertical 21-tap box of SAD. Thread = (d = tid&63, wloc = tid>>6).
// 21-deep REGISTER ring (inner loop unrolled 21x -> static slots), no smem,
// no syncs. fp32 running sum. grid (WW/4=128, NIMGB), 256 threads.
// V written d-contiguous: [h][w][d].
// ---------------------------------------------------------------------------
__global__ void __launch_bounds__(256) kvert() {
    int tid  = threadIdx.x;            // 0..255
    int d    = tid & 63;
    int wloc = tid >> 6;               // 0..3
    int imgb = blockIdx.y;
    int w    = blockIdx.x * 4 + wloc;

    const uint2* __restrict__ L =
        reinterpret_cast<const uint2*>(g_normh + (size_t)(imgb * 2 + 0) * HW * 2);
    const uint2* __restrict__ R =
        reinterpret_cast<const uint2*>(g_normh + (size_t)(imgb * 2 + 1) * HW * 2);
    __half* __restrict__ V = g_V + (size_t)imgb * HH * WW * NDISP + (size_t)w * NDISP + d;

    float ring[21];
#pragma unroll
    for (int s = 0; s < 21; ++s) ring[s] = 0.0f;

    int rw = w - d;
    bool valid = (rw >= 0);
    float run = 0.0f;

    // 336 = 16*21 iterations; j>=HH contributes dn=0, outputs guarded h<HH.
    for (int jb = 0; jb < 336; jb += 21) {
#pragma unroll
        for (int s = 0; s < 21; ++s) {
            int j = jb + s;
            float dn = 0.0f;
            if (j < HH) {
                uint2 lu = L[j * WW + w];
                __half2 l01 = *reinterpret_cast<__half2*>(&lu.x);
                __half2 l2p = *reinterpret_cast<__half2*>(&lu.y);
                float2 lf = __half22float2(l01);
                float l2 = __low2float(l2p);
                float r0 = 0.f, r1 = 0.f, r2 = 0.f;
                if (valid) {
                    uint2 ru = R[j * WW + rw];
                    __half2 r01 = *reinterpret_cast<__half2*>(&ru.x);
                    __half2 r2p = *reinterpret_cast<__half2*>(&ru.y);
                    float2 rf = __half22float2(r01);
                    r0 = rf.x; r1 = rf.y; r2 = __low2float(r2p);
                }
                dn = fabsf(lf.x - r0) + fabsf(lf.y - r1) + fabsf(l2 - r2);
            }
            run += dn - ring[s];
            ring[s] = dn;
            int h = j - RAD;
            if (h >= 0 && h < HH) V[(size_t)h * (WW * NDISP)] = __float2half_rn(run);
        }
    }
}

// ---------------------------------------------------------------------------
// K3: horizontal 21-tap box + argmin. CTA = (imgb, row). 512 threads:
// thread = (oct = t>>4 owning 16 consecutive w, dpg = t&15 owning one d-pair
// per pass). Two passes over d halves. Smem rows padded to 17 words:
// compute banks = 16*(oct&1) + dpg -> all 32 distinct. uint2 staging is
// conflict-free for stride 17. Exact argmin tie-break via packed
// (costbits<<32 | d) shfl-min over the 16 dpg lanes.
// ---------------------------------------------------------------------------
#define SW 17

__global__ void __launch_bounds__(512) khoriz() {
    __shared__ unsigned sm[WW * SW];   // 34.8 KB

    int t    = threadIdx.x;            // 0..511
    int oct  = t >> 4;                 // 0..31
    int dpg  = t & 15;                 // 0..15
    int imgb = blockIdx.y;
    int h    = blockIdx.x;
    int wb   = oct * 16;

    const uint2* __restrict__ G2 = reinterpret_cast<const uint2*>(
        g_V + ((size_t)(imgb * HH + h) * WW) * NDISP);

    float bestc[16];
    int   bestd[16];
#pragma unroll
    for (int i = 0; i < 16; ++i) { bestc[i] = FLT_MAX; bestd[i] = 0; }

#pragma unroll
    for (int pass = 0; pass < 2; ++pass) {
        __syncthreads();
        // stage d-pair words [pass*16, pass*16+16) for all 512 w (uint2 = 2 words)
#pragma unroll
        for (int k = t; k < 4096; k += 512) {
            int w = k >> 3, q = k & 7;
            uint2 v = G2[w * 16 + pass * 8 + q];
            unsigned* dst = &sm[w * SW + q * 2];
            dst[0] = v.x; dst[1] = v.y;
        }
        __syncthreads();

        int dbase = (pass * 16 + dpg) * 2;       // actual disparity (even)

        // initial window for w = wb: taps [wb-10, wb+10] clamped
        float sx = 0.f, sy = 0.f;
#pragma unroll
        for (int u = 0; u < 21; ++u) {
            int ww = wb - RAD + u;
            if (ww >= 0 && ww < WW) {
                float2 f = __half22float2(
                    *reinterpret_cast<const __half2*>(&sm[ww * SW + dpg]));
                sx += f.x; sy += f.y;
            }
        }
        int w = wb;
#pragma unroll
        for (int i = 0; i < 16; ++i) {
            if (sx < bestc[i]) { bestc[i] = sx; bestd[i] = dbase; }
            if (sy < bestc[i]) { bestc[i] = sy; bestd[i] = dbase + 1; }
            int add = w + RAD + 1;
            int sub = w - RAD;
            if (add < WW) {
                float2 f = __half22float2(
                    *reinterpret_cast<const __half2*>(&sm[add * SW + dpg]));
                sx += f.x; sy += f.y;
            }
            if (sub >= 0) {
                float2 f = __half22float2(
                    *reinterpret_cast<const __half2*>(&sm[sub * SW + dpg]));
                sx -= f.x; sy -= f.y;
            }
            ++w;
        }
    }

    // reduce over the 16 dpg lanes -- packed min keeps smallest d on tie
    float* __restrict__ D = g_disp + (imgb * HH + h) * WW;
#pragma unroll
    for (int i = 0; i < 16; ++i) {
        unsigned long long key =
            ((unsigned long long)__float_as_uint(bestc[i]) << 32) | (unsigned)bestd[i];
#pragma unroll
        for (int m = 8; m >= 1; m >>= 1) {
            unsigned long long o = __shfl_xor_sync(0xffffffffu, key, m, 16);
            if (o < key) key = o;
        }
        if (dpg == 0) D[wb + i] = (float)(unsigned)(key & 0xffffffffULL);
    }
}

// ---------------------------------------------------------------------------
// K4/K5: deterministic two-stage reduction of |disp_x - disp_gt|.
// ---------------------------------------------------------------------------
__global__ void kred1() {
    __shared__ float sm[256];
    const int N = 2 * HW;
    int tid = threadIdx.x;
    float s = 0.0f;
    for (int p = blockIdx.x * 256 + tid; p < N; p += 256 * 256)
        s += fabsf(g_disp[p] - g_disp[2 * HW + p]);
    sm[tid] = s;
    __syncthreads();
    for (int o = 128; o > 0; o >>= 1) {
        if (tid < o) sm[tid] += sm[tid + o];
        __syncthreads();
    }
    if (tid == 0) g_part[blockIdx.x] = sm[0];
}

__global__ void kred2(float* __restrict__ out) {
    __shared__ float sm[256];
    int tid = threadIdx.x;
    sm[tid] = g_part[tid];
    __syncthreads();
    for (int o = 128; o > 0; o >>= 1) {
        if (tid < o) sm[tid] += sm[tid + o];
        __syncthreads();
    }
    if (tid == 0) out[0] = sm[0] / (float)(2 * HW);
}

// ---------------------------------------------------------------------------
extern "C" void kernel_launch(void* const* d_in, const int* in_sizes, int n_in,
                              void* d_out, int out_size) {
    const float* x  = (const float*)d_in[0];
    const float* gt = (const float*)d_in[1];
    float* out = (float*)d_out;

    int nNorm = NIMGB * 2 * HW;
    knorm<<<(nNorm + 255) / 256, 256>>>(x, gt);
    kvert<<<dim3(WW / 4, NIMGB), 256>>>();
    khoriz<<<dim3(HH, NIMGB), 512>>>();
    kred1<<<256, 256>>>();
    kred2<<<1, 256>>>(out);
}

// round 7
// speedup vs baseline: 2.3477x; 1.2195x over previous
#include <cuda_runtime.h>
#include <cuda_fp16.h>
#include <math.h>
#include <float.h>

#define HH 320
#define WW 512
#define HW (HH * WW)
#define NDISP 64
#define RAD 10
#define NIMGB 4
#define DPB 8              // disparities per CTA
#define HB 40              // output rows per band
#define NB (HH / HB)       // 8 bands

// Scratch (device globals -- allocation-free rule)
__device__ __align__(16) __half2 g_normh[NIMGB * 2 * HW * 2];  // packed (c0c1)(c2,0), 10.5 MB
__device__ unsigned long long g_key[NIMGB * HW];               // (costbits<<32)|d, 5.2 MB
__device__ float g_part[256];

// ---------------------------------------------------------------------------
// K1: L2-normalize, output packed fp16 (4 halves per pixel per side).
// ---------------------------------------------------------------------------
__global__ void knorm(const float* __restrict__ x, const float* __restrict__ gt) {
    int idx = blockIdx.x * blockDim.x + threadIdx.x;
    const int total = NIMGB * 2 * HW;
    if (idx >= total) return;
    int pix  = idx % HW;
    int rest = idx / HW;
    int side = rest & 1;
    int imgb = rest >> 1;
    int img  = imgb >> 1;
    int b    = imgb & 1;

    const float* src = img ? gt : x;
    int base = (b * 6 + side * 3) * HW + pix;
    float v0 = src[base];
    float v1 = src[base + HW];
    float v2 = src[base + 2 * HW];
    float n = sqrtf(v0 * v0 + v1 * v1 + v2 * v2);
    float inv = 1.0f / fmaxf(n, 1e-12f);

    __half2 a = __floats2half2_rn(v0 * inv, v1 * inv);
    __half2 c = __floats2half2_rn(v2 * inv, 0.0f);
    uint2 pk;
    pk.x = *reinterpret_cast<unsigned*>(&a);
    pk.y = *reinterpret_cast<unsigned*>(&c);
    uint2* dst = reinterpret_cast<uint2*>(g_normh + ((size_t)(imgb * 2 + side) * HW + pix) * 2);
    *dst = pk;
}

// ---------------------------------------------------------------------------
// K-init: poison keys to u64-max. 640 blocks x 256 thr x 4 = 655,360 = NIMGB*HW ✓
// ---------------------------------------------------------------------------
__global__ void kinit() {
    int i = (blockIdx.x * 256 + threadIdx.x) * 4;
#pragma unroll
    for (int q = 0; q < 4; ++q) g_key[i + q] = ~0ull;
}

__global__ void kdummy() {}   // shifts the ncu capture slot onto kfused

// ---------------------------------------------------------------------------
// KFUSED: per (imgb, d-block of 8, 40-row band). Thread = w (512).
// Vertical 21-tap box via fp32 running sums with bit-exact SAD recompute at
// add (jadd) and subtract (jsub = jadd-21) edges -- no history storage.
// Subtract fires only for rows this CTA actually added: step >= 21 (i.e.
// jsub >= h0-RAD) AND 0 <= jsub < HH.   [R6 bug: missing step>=21 guard]
// Horizontal 21-tap box via warp shfl prefix scan + cross-warp warp-total.
// Per-(h,w) argmin over all 64 d via packed u64 atomicMin (deterministic,
// first-index tie-break preserved).
// ---------------------------------------------------------------------------
__global__ void __launch_bounds__(512) kfused() {
    __shared__ float Psm[DPB][WW];     // 16 KB
    __shared__ float Ssm[16][DPB];     // warp totals

    int w    = threadIdx.x;            // 0..511
    int lane = w & 31;
    int wid  = w >> 5;
    int h0   = blockIdx.x * HB;
    int d0   = blockIdx.y * DPB;
    int imgb = blockIdx.z;

    const uint2* __restrict__ L =
        reinterpret_cast<const uint2*>(g_normh + (size_t)(imgb * 2 + 0) * HW * 2);
    const uint2* __restrict__ R =
        reinterpret_cast<const uint2*>(g_normh + (size_t)(imgb * 2 + 1) * HW * 2);
    unsigned long long* __restrict__ K = g_key + imgb * HW;

    float runV[DPB];
#pragma unroll
    for (int k = 0; k < DPB; ++k) runV[k] = 0.0f;
    const int rwb = w - d0;

    for (int step = 0; step < HB + 2 * RAD; ++step) {
        int jadd = h0 - RAD + step;
        int jsub = jadd - 21;

        // ---- add edge: row jadd ----
        if (jadd >= 0 && jadd < HH) {
            uint2 lu = L[jadd * WW + w];
            __half2 l01 = *reinterpret_cast<__half2*>(&lu.x);
            __half2 l2p = *reinterpret_cast<__half2*>(&lu.y);
            float2 lf = __half22float2(l01);
            float l2 = __low2float(l2p);
            float labs = fabsf(lf.x) + fabsf(lf.y) + fabsf(l2);
            uint2 ru[DPB];
#pragma unroll
            for (int k = 0; k < DPB; ++k) {
                int rw = rwb - k;
                ru[k] = (rw >= 0) ? R[jadd * WW + rw] : make_uint2(0u, 0u);
            }
#pragma unroll
            for (int k = 0; k < DPB; ++k) {
                int rw = rwb - k;
                float dn;
                if (rw >= 0) {
                    __half2 r01 = *reinterpret_cast<__half2*>(&ru[k].x);
                    __half2 r2p = *reinterpret_cast<__half2*>(&ru[k].y);
                    float2 rf = __half22float2(r01);
                    float r2 = __low2float(r2p);
                    dn = fabsf(lf.x - rf.x) + fabsf(lf.y - rf.y) + fabsf(l2 - r2);
                } else dn = labs;
                runV[k] += dn;
            }
        }
        // ---- subtract edge: row jsub (bit-identical recompute) ----
        // Only rows previously ADDED by this CTA: step>=21 <=> jsub >= h0-RAD.
        if (step >= 21 && jsub >= 0 && jsub < HH) {
            uint2 lu = L[jsub * WW + w];
            __half2 l01 = *reinterpret_cast<__half2*>(&lu.x);
            __half2 l2p = *reinterpret_cast<__half2*>(&lu.y);
            float2 lf = __half22float2(l01);
            float l2 = __low2float(l2p);
            float labs = fabsf(lf.x) + fabsf(lf.y) + fabsf(l2);
            uint2 ru[DPB];
#pragma unroll
            for (int k = 0; k < DPB; ++k) {
                int rw = rwb - k;
                ru[k] = (rw >= 0) ? R[jsub * WW + rw] : make_uint2(0u, 0u);
            }
#pragma unroll
            for (int k = 0; k < DPB; ++k) {
                int rw = rwb - k;
                float dn;
                if (rw >= 0) {
                    __half2 r01 = *reinterpret_cast<__half2*>(&ru[k].x);
                    __half2 r2p = *reinterpret_cast<__half2*>(&ru[k].y);
                    float2 rf = __half22float2(r01);
                    float r2 = __low2float(r2p);
                    dn = fabsf(lf.x - rf.x) + fabsf(lf.y - rf.y) + fabsf(l2 - r2);
                } else dn = labs;
                runV[k] -= dn;
            }
        }

        int h = jadd - RAD;
        if (h >= h0) {                  // uniform across CTA
            __syncthreads();            // protect Psm/Ssm WAR from previous step
#pragma unroll
            for (int k = 0; k < DPB; ++k) {
                float v = runV[k];
#pragma unroll
                for (int dlt = 1; dlt < 32; dlt <<= 1) {
                    float t = __shfl_up_sync(0xffffffffu, v, dlt);
                    if (lane >= dlt) v += t;
                }
                Psm[k][w] = v;
                if (lane == 31) Ssm[wid][k] = v;
            }
            __syncthreads();

            int a  = (w + RAD > WW - 1) ? (WW - 1) : (w + RAD);
            int b  = w - RAD - 1;
            int wa = a >> 5;
            float bc = FLT_MAX; int bd = 0;
#pragma unroll
            for (int k = 0; k < DPB; ++k) {
                float Pa = Psm[k][a];
                float Pb = 0.0f; int wb = wa;
                if (b >= 0) { Pb = Psm[k][b]; wb = b >> 5; }
                float s = (wa != wb) ? Ssm[wb][k] : 0.0f;
                float Hc = Pa - Pb + s;
                if (Hc < bc) { bc = Hc; bd = d0 + k; }
            }
            bc = fmaxf(bc, 0.0f);
            unsigned long long key =
                ((unsigned long long)__float_as_uint(bc) << 32) | (unsigned)bd;
            atomicMin(&K[h * WW + w], key);
        }
    }
}

// ---------------------------------------------------------------------------
// K4/K5: deterministic two-stage reduction of |d_x - d_gt| from packed keys.
// ---------------------------------------------------------------------------
__global__ void kred1() {
    __shared__ float sm[256];
    const int N = 2 * HW;
    int tid = threadIdx.x;
    float s = 0.0f;
    for (int p = blockIdx.x * 256 + tid; p < N; p += 256 * 256) {
        int dx = (int)(unsigned)(g_key[p] & 0xffffffffull);
        int dg = (int)(unsigned)(g_key[2 * HW + p] & 0xffffffffull);
        s += fabsf((float)(dx - dg));
    }
    sm[tid] = s;
    __syncthreads();
    for (int o = 128; o > 0; o >>= 1) {
        if (tid < o) sm[tid] += sm[tid + o];
        __syncthreads();
    }
    if (tid == 0) g_part[blockIdx.x] = sm[0];
}

__global__ void kred2(float* __restrict__ out) {
    __shared__ float sm[256];
    int tid = threadIdx.x;
    sm[tid] = g_part[tid];
    __syncthreads();
    for (int o = 128; o > 0; o >>= 1) {
        if (tid < o) sm[tid] += sm[tid + o];
        __syncthreads();
    }
    if (tid == 0) out[0] = sm[0] / (float)(2 * HW);
}

// ---------------------------------------------------------------------------
extern "C" void kernel_launch(void* const* d_in, const int* in_sizes, int n_in,
                              void* d_out, int out_size) {
    const float* x  = (const float*)d_in[0];
    const float* gt = (const float*)d_in[1];
    float* out = (float*)d_out;

    int nNorm = NIMGB * 2 * HW;
    knorm<<<(nNorm + 255) / 256, 256>>>(x, gt);
    kinit<<<640, 256>>>();
    kdummy<<<1, 32>>>();                              // capture-slot shim
    kfused<<<dim3(NB, NDISP / DPB, NIMGB), 512>>>();  // launch #4 (profiled slot)
    kred1<<<256, 256>>>();
    kred2<<<1, 256>>>(out);
}

// round 8
// speedup vs baseline: 2.7722x; 1.1808x over previous
#include <cuda_runtime.h>
#include <cuda_fp16.h>
#include <math.h>
#include <float.h>

#define HH 320
#define WW 512
#define HW (HH * WW)
#define NDISP 64
#define RAD 10
#define NIMGB 4
#define DPB 4              // disparities per CTA
#define NDG (NDISP / DPB)  // 16 d-groups
#define HB 40              // output rows per band
#define NB (HH / HB)       // 8 bands

// Padded image layout (uint2 = 4 packed halves per pixel): row stride 576
// (64 zero pad cols + 512), 340 rows (10 zero pad top + 320 + 10 zero pad bot).
#define STR  576
#define PADX 64
#define PADY 10
#define ROWS 340

// Scratch (device globals -- allocation-free rule)
__device__ __align__(16) uint2 g_pad[NIMGB * 2 * ROWS * STR];   // 12.5 MB
__device__ unsigned long long g_key[NIMGB * HW];                // (costbits<<32)|d
__device__ float g_part[256];

// ---------------------------------------------------------------------------
// K1: L2-normalize into padded layout; pad cells written as zeros.
// One thread per padded slot: NIMGB*2*340*576 = 1,566,720 = 6120 * 256.
// ---------------------------------------------------------------------------
__global__ void knorm(const float* __restrict__ x, const float* __restrict__ gt) {
    int idx = blockIdx.x * 256 + threadIdx.x;
    int wp   = idx % STR;
    int rest = idx / STR;
    int jp   = rest % ROWS;
    int rest2 = rest / ROWS;
    int side = rest2 & 1;
    int imgb = rest2 >> 1;

    uint2 pk = make_uint2(0u, 0u);
    int w = wp - PADX, h = jp - PADY;
    if (w >= 0 && h >= 0 && h < HH) {     // w < 512 always (wp <= 575)
        int img = imgb >> 1;
        int b   = imgb & 1;
        const float* src = img ? gt : x;
        int base = (b * 6 + side * 3) * HW + h * WW + w;
        float v0 = src[base];
        float v1 = src[base + HW];
        float v2 = src[base + 2 * HW];
        float n = sqrtf(v0 * v0 + v1 * v1 + v2 * v2);
        float inv = 1.0f / fmaxf(n, 1e-12f);
        __half2 a = __floats2half2_rn(v0 * inv, v1 * inv);
        __half2 c = __floats2half2_rn(v2 * inv, 0.0f);
        pk.x = *reinterpret_cast<unsigned*>(&a);
        pk.y = *reinterpret_cast<unsigned*>(&c);
    }
    g_pad[idx] = pk;
}

// ---------------------------------------------------------------------------
// K-init: poison keys to u64-max. 640 x 256 x 4 = 655,360 = NIMGB*HW ✓
// ---------------------------------------------------------------------------
__global__ void kinit() {
    int i = (blockIdx.x * 256 + threadIdx.x) * 4;
#pragma unroll
    for (int q = 0; q < 4; ++q) g_key[i + q] = ~0ull;
}

__global__ void kdummy() {}   // keeps kfused in the profiled launch slot (#4)

// ---------------------------------------------------------------------------
// KFUSED: per (band, d-group of 4, imgb) CTA; thread = w. Branchless edges
// thanks to zero padding; half2 SAD; fp32 vertical running sums with
// bit-exact add/sub edge recompute; warp shfl prefix scan for the
// horizontal 21-tap box; packed u64 atomicMin argmin (first-index ties).
// ---------------------------------------------------------------------------
__global__ void __launch_bounds__(512) kfused() {
    __shared__ float Psm[DPB][WW];     // 8 KB
    __shared__ float Ssm[16][DPB];

    const int w    = threadIdx.x;      // 0..511
    const int lane = w & 31;
    const int wid  = w >> 5;
    const int h0   = blockIdx.x * HB;
    const int d0   = blockIdx.y * DPB;
    const int imgb = blockIdx.z;

    const uint2* __restrict__ Lb = g_pad + (size_t)(imgb * 2 + 0) * ROWS * STR + PADX + w;
    const uint2* __restrict__ Rb = g_pad + (size_t)(imgb * 2 + 1) * ROWS * STR + PADX + (w - d0);
    unsigned long long* __restrict__ K = g_key + imgb * HW;

    float runV[DPB];
#pragma unroll
    for (int k = 0; k < DPB; ++k) runV[k] = 0.0f;

    auto edge = [&](int j, float sgn) {
        const uint2* Lp = Lb + (j + PADY) * STR;
        const uint2* Rp = Rb + (j + PADY) * STR;
        uint2 lu = *Lp;
        __half2 lA = *reinterpret_cast<__half2*>(&lu.x);
        __half2 lB = *reinterpret_cast<__half2*>(&lu.y);
#pragma unroll
        for (int k = 0; k < DPB; ++k) {
            uint2 ru = Rp[-k];
            __half2 rA = *reinterpret_cast<__half2*>(&ru.x);
            __half2 rB = *reinterpret_cast<__half2*>(&ru.y);
            __half2 s = __hadd2(__habs2(__hsub2(lA, rA)), __habs2(__hsub2(lB, rB)));
            float dn = __half2float(__hadd(__low2half(s), __high2half(s)));
            runV[k] = fmaf(sgn, dn, runV[k]);
        }
    };

    auto emit = [&](int h) {
        __syncthreads();                // WAR vs previous emit's reads
#pragma unroll
        for (int k = 0; k < DPB; ++k) {
            float v = runV[k];
#pragma unroll
            for (int dlt = 1; dlt < 32; dlt <<= 1) {
                float t = __shfl_up_sync(0xffffffffu, v, dlt);
                if (lane >= dlt) v += t;
            }
            Psm[k][w] = v;
            if (lane == 31) Ssm[wid][k] = v;
        }
        __syncthreads();

        int a  = (w + RAD > WW - 1) ? (WW - 1) : (w + RAD);
        int b  = w - RAD - 1;
        int wa = a >> 5;
        float bc = FLT_MAX; int bd = 0;
#pragma unroll
        for (int k = 0; k < DPB; ++k) {
            float Pa = Psm[k][a];
            float Pb = 0.0f; int wb = wa;
            if (b >= 0) { Pb = Psm[k][b]; wb = b >> 5; }
            float s = (wa != wb) ? Ssm[wb][k] : 0.0f;
            float Hc = Pa - Pb + s;
            if (Hc < bc) { bc = Hc; bd = d0 + k; }
        }
        bc = fmaxf(bc, 0.0f);
        unsigned long long key =
            ((unsigned long long)__float_as_uint(bc) << 32) | (unsigned)bd;
        atomicMin(&K[h * WW + w], key);
    };

    // warm-up: fill the vertical window (adds for rows h0-10 .. h0+9)
    for (int sstep = 0; sstep < 2 * RAD; ++sstep)
        edge(h0 - RAD + sstep, 1.0f);
    // first output row
    edge(h0 + RAD, 1.0f);
    emit(h0);
    // steady state: add row h+10, subtract row h-11, emit h
    for (int h = h0 + 1; h < h0 + HB; ++h) {
        edge(h + RAD, 1.0f);
        edge(h - RAD - 1, -1.0f);
        emit(h);
    }
}

// ---------------------------------------------------------------------------
// K4/K5: deterministic two-stage reduction of |d_x - d_gt| from packed keys.
// ---------------------------------------------------------------------------
__global__ void kred1() {
    __shared__ float sm[256];
    const int N = 2 * HW;
    int tid = threadIdx.x;
    float s = 0.0f;
    for (int p = blockIdx.x * 256 + tid; p < N; p += 256 * 256) {
        int dx = (int)(unsigned)(g_key[p] & 0xffffffffull);
        int dg = (int)(unsigned)(g_key[2 * HW + p] & 0xffffffffull);
        s += fabsf((float)(dx - dg));
    }
    sm[tid] = s;
    __syncthreads();
    for (int o = 128; o > 0; o >>= 1) {
        if (tid < o) sm[tid] += sm[tid + o];
        __syncthreads();
    }
    if (tid == 0) g_part[blockIdx.x] = sm[0];
}

__global__ void kred2(float* __restrict__ out) {
    __shared__ float sm[256];
    int tid = threadIdx.x;
    sm[tid] = g_part[tid];
    __syncthreads();
    for (int o = 128; o > 0; o >>= 1) {
        if (tid < o) sm[tid] += sm[tid + o];
        __syncthreads();
    }
    if (tid == 0) out[0] = sm[0] / (float)(2 * HW);
}

// ---------------------------------------------------------------------------
extern "C" void kernel_launch(void* const* d_in, const int* in_sizes, int n_in,
                              void* d_out, int out_size) {
    const float* x  = (const float*)d_in[0];
    const float* gt = (const float*)d_in[1];
    float* out = (float*)d_out;

    knorm<<<6120, 256>>>(x, gt);                       // 6120*256 = NIMGB*2*ROWS*STR
    kinit<<<640, 256>>>();
    kdummy<<<1, 32>>>();                               // capture-slot shim
    kfused<<<dim3(NB, NDG, NIMGB), 512>>>();           // launch #4 (profiled slot)
    kred1<<<256, 256>>>();
    kred2<<<1, 256>>>(out);
}

// round 9
// speedup vs baseline: 3.1163x; 1.1241x over previous
#include <cuda_runtime.h>
#include <cuda_fp16.h>
#include <math.h>
#include <float.h>

#define HH 320
#define WW 512
#define HW (HH * WW)
#define NDISP 64
#define RAD 10
#define NIMGB 4
#define DPB 4              // disparities per CTA
#define NDG (NDISP / DPB)  // 16 d-groups
#define HB 20              // output rows per band (wave-balance: 1024 CTAs)
#define NB (HH / HB)       // 16 bands

// Padded image layout (uint2 = 4 packed halves per pixel): row stride 576
// (64 zero pad cols + 512), 340 rows (10 zero pad top + 320 + 10 zero pad bot).
#define STR  576
#define PADX 64
#define PADY 10
#define ROWS 340

// Scratch (device globals -- allocation-free rule)
__device__ __align__(16) uint2 g_pad[NIMGB * 2 * ROWS * STR];   // 12.5 MB
__device__ unsigned long long g_key[NIMGB * HW];                // (costbits<<32)|d
__device__ float g_part[256];

// ---------------------------------------------------------------------------
// K1: L2-normalize into padded layout; pad cells written as zeros.
// One thread per padded slot: NIMGB*2*340*576 = 1,566,720 = 6120 * 256.
// ---------------------------------------------------------------------------
__global__ void knorm(const float* __restrict__ x, const float* __restrict__ gt) {
    int idx = blockIdx.x * 256 + threadIdx.x;
    int wp   = idx % STR;
    int rest = idx / STR;
    int jp   = rest % ROWS;
    int rest2 = rest / ROWS;
    int side = rest2 & 1;
    int imgb = rest2 >> 1;

    uint2 pk = make_uint2(0u, 0u);
    int w = wp - PADX, h = jp - PADY;
    if (w >= 0 && h >= 0 && h < HH) {     // w < 512 always (wp <= 575)
        int img = imgb >> 1;
        int b   = imgb & 1;
        const float* src = img ? gt : x;
        int base = (b * 6 + side * 3) * HW + h * WW + w;
        float v0 = src[base];
        float v1 = src[base + HW];
        float v2 = src[base + 2 * HW];
        float n = sqrtf(v0 * v0 + v1 * v1 + v2 * v2);
        float inv = 1.0f / fmaxf(n, 1e-12f);
        __half2 a = __floats2half2_rn(v0 * inv, v1 * inv);
        __half2 c = __floats2half2_rn(v2 * inv, 0.0f);
        pk.x = *reinterpret_cast<unsigned*>(&a);
        pk.y = *reinterpret_cast<unsigned*>(&c);
    }
    g_pad[idx] = pk;
}

// ---------------------------------------------------------------------------
// K-init: poison keys to u64-max. 640 x 256 x 4 = 655,360 = NIMGB*HW ✓
// ---------------------------------------------------------------------------
__global__ void kinit() {
    int i = (blockIdx.x * 256 + threadIdx.x) * 4;
#pragma unroll
    for (int q = 0; q < 4; ++q) g_key[i + q] = ~0ull;
}

__global__ void kdummy() {}   // keeps kfused in the profiled launch slot (#4)

// ---------------------------------------------------------------------------
// KFUSED: per (band, d-group of 4, imgb) CTA; thread = w. Branchless edges
// thanks to zero padding; half2 SAD; fp32 vertical running sums with
// bit-exact add/sub edge recompute; warp shfl prefix scan for the
// horizontal 21-tap box; packed u64 atomicMin argmin (first-index ties).
// launch_bounds(512,4): regs<=32 -> 4 CTAs/SM (full occupancy), and
// HB=20 -> 1024 CTAs -> 6.92 avg / 7 max CTAs per SM (no wave tail).
// ---------------------------------------------------------------------------
__global__ void __launch_bounds__(512, 4) kfused() {
    __shared__ float Psm[DPB][WW];     // 8 KB
    __shared__ float Ssm[16][DPB];

    const int w    = threadIdx.x;      // 0..511
    const int lane = w & 31;
    const int wid  = w >> 5;
    const int h0   = blockIdx.x * HB;
    const int d0   = blockIdx.y * DPB;
    const int imgb = blockIdx.z;

    const uint2* __restrict__ Lb = g_pad + (size_t)(imgb * 2 + 0) * ROWS * STR + PADX + w;
    const uint2* __restrict__ Rb = g_pad + (size_t)(imgb * 2 + 1) * ROWS * STR + PADX + (w - d0);
    unsigned long long* __restrict__ K = g_key + imgb * HW;

    float runV[DPB];
#pragma unroll
    for (int k = 0; k < DPB; ++k) runV[k] = 0.0f;

    auto edge = [&](int j, float sgn) {
        const uint2* Lp = Lb + (j + PADY) * STR;
        const uint2* Rp = Rb + (j + PADY) * STR;
        uint2 lu = *Lp;
        __half2 lA = *reinterpret_cast<__half2*>(&lu.x);
        __half2 lB = *reinterpret_cast<__half2*>(&lu.y);
#pragma unroll
        for (int k = 0; k < DPB; ++k) {
            uint2 ru = Rp[-k];
            __half2 rA = *reinterpret_cast<__half2*>(&ru.x);
            __half2 rB = *reinterpret_cast<__half2*>(&ru.y);
            __half2 s = __hadd2(__habs2(__hsub2(lA, rA)), __habs2(__hsub2(lB, rB)));
            float dn = __half2float(__hadd(__low2half(s), __high2half(s)));
            runV[k] = fmaf(sgn, dn, runV[k]);
        }
    };

    auto emit = [&](int h) {
        __syncthreads();                // WAR vs previous emit's reads
#pragma unroll
        for (int k = 0; k < DPB; ++k) {
            float v = runV[k];
#pragma unroll
            for (int dlt = 1; dlt < 32; dlt <<= 1) {
                float t = __shfl_up_sync(0xffffffffu, v, dlt);
                if (lane >= dlt) v += t;
            }
            Psm[k][w] = v;
            if (lane == 31) Ssm[wid][k] = v;
        }
        __syncthreads();

        int a  = (w + RAD > WW - 1) ? (WW - 1) : (w + RAD);
        int b  = w - RAD - 1;
        int wa = a >> 5;
        float bc = FLT_MAX; int bd = 0;
#pragma unroll
        for (int k = 0; k < DPB; ++k) {
            float Pa = Psm[k][a];
            float Pb = 0.0f; int wb = wa;
            if (b >= 0) { Pb = Psm[k][b]; wb = b >> 5; }
            float s = (wa != wb) ? Ssm[wb][k] : 0.0f;
            float Hc = Pa - Pb + s;
            if (Hc < bc) { bc = Hc; bd = d0 + k; }
        }
        bc = fmaxf(bc, 0.0f);
        unsigned long long key =
            ((unsigned long long)__float_as_uint(bc) << 32) | (unsigned)bd;
        atomicMin(&K[h * WW + w], key);
    };

    // warm-up: fill the vertical window (adds for rows h0-10 .. h0+9)
    for (int sstep = 0; sstep < 2 * RAD; ++sstep)
        edge(h0 - RAD + sstep, 1.0f);
    // first output row
    edge(h0 + RAD, 1.0f);
    emit(h0);
    // steady state: add row h+10, subtract row h-11, emit h
    for (int h = h0 + 1; h < h0 + HB; ++h) {
        edge(h + RAD, 1.0f);
        edge(h - RAD - 1, -1.0f);
        emit(h);
    }
}

// ---------------------------------------------------------------------------
// K4/K5: deterministic two-stage reduction of |d_x - d_gt| from packed keys.
// ---------------------------------------------------------------------------
__global__ void kred1() {
    __shared__ float sm[256];
    const int N = 2 * HW;
    int tid = threadIdx.x;
    float s = 0.0f;
    for (int p = blockIdx.x * 256 + tid; p < N; p += 256 * 256) {
        int dx = (int)(unsigned)(g_key[p] & 0xffffffffull);
        int dg = (int)(unsigned)(g_key[2 * HW + p] & 0xffffffffull);
        s += fabsf((float)(dx - dg));
    }
    sm[tid] = s;
    __syncthreads();
    for (int o = 128; o > 0; o >>= 1) {
        if (tid < o) sm[tid] += sm[tid + o];
        __syncthreads();
    }
    if (tid == 0) g_part[blockIdx.x] = sm[0];
}

__global__ void kred2(float* __restrict__ out) {
    __shared__ float sm[256];
    int tid = threadIdx.x;
    sm[tid] = g_part[tid];
    __syncthreads();
    for (int o = 128; o > 0; o >>= 1) {
        if (tid < o) sm[tid] += sm[tid + o];
        __syncthreads();
    }
    if (tid == 0) out[0] = sm[0] / (float)(2 * HW);
}

// ---------------------------------------------------------------------------
extern "C" void kernel_launch(void* const* d_in, const int* in_sizes, int n_in,
                              void* d_out, int out_size) {
    const float* x  = (const float*)d_in[0];
    const float* gt = (const float*)d_in[1];
    float* out = (float*)d_out;

    knorm<<<6120, 256>>>(x, gt);                       // 6120*256 = NIMGB*2*ROWS*STR
    kinit<<<640, 256>>>();
    kdummy<<<1, 32>>>();                               // capture-slot shim
    kfused<<<dim3(NB, NDG, NIMGB), 512>>>();           // launch #4 (profiled slot)
    kred1<<<256, 256>>>();
    kred2<<<1, 256>>>(out);
}